// round 1
// baseline (speedup 1.0000x reference)
#include <cuda_runtime.h>
#include <cstdint>

#define BB 64
#define TT 1024
#define DD 64
#define HH 256
#define NGROUPS 8
#define NSLICES 16
#define BPG 8      // batches per group
#define UPS 16     // hidden units per slice
#define NCTAS (NGROUPS*NSLICES)
#define NTHREADS 128

// ---------------- device-global scratch (no runtime allocation allowed) ----------------
__device__ float    d_h1s[(size_t)TT * BB * HH];   // layer-0 hidden stream [T][B][H]
__device__ float    d_h2s[(size_t)TT * BB * HH];   // layer-1 hidden stream [T][B][H]
__device__ float    d_hbuf[2 * BB * HH];           // ping-pong h state
__device__ unsigned d_cnt[NGROUPS * 32];           // barrier arrive counters (128B apart)
__device__ unsigned d_gen[NGROUPS * 32];           // barrier generations

// Barrier across the 16 CTAs of one batch group. Sense-free generation barrier;
// gen is monotonic so it is safe across graph replays and across the two layer launches.
__device__ __forceinline__ void group_barrier(int g) {
    __syncthreads();
    if (threadIdx.x == 0) {
        __threadfence();
        unsigned* cnt = &d_cnt[g * 32];
        unsigned* gen = &d_gen[g * 32];
        unsigned my = *(volatile unsigned*)gen;
        unsigned arrived = atomicAdd(cnt, 1u);
        if (arrived == NSLICES - 1) {
            atomicExch(cnt, 0u);
            __threadfence();
            atomicAdd(gen, 1u);
        } else {
            while (*(volatile unsigned*)gen == my) __nanosleep(64);
        }
        __threadfence();
    }
    __syncthreads();
}

__device__ __forceinline__ float sigf(float x) { return 1.f / (1.f + expf(-x)); }

// One LSTM layer, persistent. gates = [x_t | h_{t-1}] @ [W_ih | W_hh]^T + (b_ih + b_hh).
// Grid: 128 CTAs = 8 batch groups x 16 hidden slices. CTA owns 64 gate rows
// (4 gates x 16 units) for 8 batch elements.
template <int KIN>
__global__ void __launch_bounds__(NTHREADS, 1) rnn_layer(
    const float* __restrict__ xin, long long SBv, long long STv,
    const float* __restrict__ Wih, const float* __restrict__ Whh,
    const float* __restrict__ bih, const float* __restrict__ bhh,
    int in_sel, int out_sel)
{
    constexpr int KTOT = KIN + HH;
    constexpr int SP   = KTOT + 4;        // padded row stride -> conflict-free LDS.128
    extern __shared__ float sm[];
    float* sW = sm;                        // [64][SP]
    float* sV = sW + 64 * SP;              // [8][KTOT]   staged [x_t | h_prev]
    float* sG = sV + 8 * KTOT;             // [64][8]     gate values
    float* sC = sG + 512;                  // [16][8]     cell state

    const float* in = in_sel ? d_h1s : xin;
    float*       hs = out_sel ? d_h2s : d_h1s;

    const int cta   = blockIdx.x;
    const int grp   = cta >> 4;            // batch group 0..7
    const int sl    = cta & 15;            // hidden slice 0..15
    const int bbase = grp * BPG;
    const int ubase = sl * UPS;
    const int tid   = threadIdx.x;

    // ---- one-time: load combined weight slice [64 rows][KIN | H] into SMEM ----
    for (int idx = tid; idx < 64 * KTOT; idx += NTHREADS) {
        int r = idx / KTOT, k = idx - r * KTOT;
        int R = ((r >> 4) << 8) + ubase + (r & 15);   // global gate row
        float v = (k < KIN) ? Wih[(long long)R * KIN + k]
                            : Whh[(long long)R * HH + (k - KIN)];
        sW[r * SP + k] = v;
    }

    const int   bq   = tid >> 6;           // batch quad (0/1)
    const int   rr   = tid & 63;           // local gate row
    const int   Rg   = ((rr >> 4) << 8) + ubase + (rr & 15);
    const float bias = bih[Rg] + bhh[Rg];

    // ---- init c = 0 and zero own slice of hbuf[0] ----
    {
        int u = tid & 15, b = tid >> 4;
        sC[u * 8 + b] = 0.f;
        d_hbuf[(bbase + b) * HH + ubase + u] = 0.f;
    }
    __threadfence();
    group_barrier(grp);    // all slices of this group zeroed; sW also visible

    for (int t = 0; t < TT; ++t) {
        const int rb = t & 1;
        const float* hrd = d_hbuf + rb * (BB * HH);
        float*       hwr = d_hbuf + (rb ^ 1) * (BB * HH);

        // ---- stage input vector [x_t | h_prev] for 8 batches ----
        constexpr int K4 = KIN / 4;
        for (int idx = tid; idx < 8 * K4; idx += NTHREADS) {
            int b = idx / K4, k4 = idx - b * K4;
            reinterpret_cast<float4*>(sV + b * KTOT)[k4] =
                reinterpret_cast<const float4*>(
                    in + (long long)(bbase + b) * SBv + (long long)t * STv)[k4];
        }
        for (int idx = tid; idx < 8 * (HH / 4); idx += NTHREADS) {
            int b = idx >> 6, k4 = idx & 63;
            reinterpret_cast<float4*>(sV + b * KTOT + KIN)[k4] =
                reinterpret_cast<const float4*>(hrd + (bbase + b) * HH)[k4];
        }
        __syncthreads();

        // ---- dot products: thread = 1 gate row x 4 batches ----
        float a0 = bias, a1 = bias, a2 = bias, a3 = bias;
        const float* wrow = sW + rr * SP;
        const float* vb   = sV + (bq * 4) * KTOT;
#pragma unroll 4
        for (int k = 0; k < KTOT; k += 4) {
            float4 w  = *reinterpret_cast<const float4*>(wrow + k);
            float4 p0 = *reinterpret_cast<const float4*>(vb + k);
            float4 p1 = *reinterpret_cast<const float4*>(vb + KTOT + k);
            float4 p2 = *reinterpret_cast<const float4*>(vb + 2 * KTOT + k);
            float4 p3 = *reinterpret_cast<const float4*>(vb + 3 * KTOT + k);
            a0 += w.x * p0.x; a0 += w.y * p0.y; a0 += w.z * p0.z; a0 += w.w * p0.w;
            a1 += w.x * p1.x; a1 += w.y * p1.y; a1 += w.z * p1.z; a1 += w.w * p1.w;
            a2 += w.x * p2.x; a2 += w.y * p2.y; a2 += w.z * p2.z; a2 += w.w * p2.w;
            a3 += w.x * p3.x; a3 += w.y * p3.y; a3 += w.z * p3.z; a3 += w.w * p3.w;
        }
        sG[rr * 8 + bq * 4 + 0] = a0;
        sG[rr * 8 + bq * 4 + 1] = a1;
        sG[rr * 8 + bq * 4 + 2] = a2;
        sG[rr * 8 + bq * 4 + 3] = a3;
        __syncthreads();

        // ---- elementwise update: thread = (unit, batch) ----
        {
            int u = tid & 15, b = tid >> 4;
            float gi = sG[(u)      * 8 + b];
            float gf = sG[(16 + u) * 8 + b];
            float gg = sG[(32 + u) * 8 + b];
            float go = sG[(48 + u) * 8 + b];
            float i = sigf(gi);
            float f = sigf(gf);
            float g = tanhf(gg);
            float o = sigf(go);
            float c = f * sC[u * 8 + b] + i * g;
            sC[u * 8 + b] = c;
            float hv = o * tanhf(c);
            hwr[(bbase + b) * HH + ubase + u] = hv;
            hs[((long long)t * BB + (bbase + b)) * HH + ubase + u] = hv;
        }
        __threadfence();
        group_barrier(grp);
    }
}

// out[b] = dot(h2[T-1][b][:], fc_w) + fc_b
__global__ void fc_kernel(const float* __restrict__ fcw,
                          const float* __restrict__ fcb,
                          float* __restrict__ out)
{
    int b = blockIdx.x, tid = threadIdx.x;
    const float* h = d_h2s + ((long long)(TT - 1) * BB + b) * HH;
    float s = 0.f;
    for (int k = tid; k < HH; k += 128) s += h[k] * fcw[k];
    for (int o = 16; o > 0; o >>= 1) s += __shfl_xor_sync(0xFFFFFFFFu, s, o);
    __shared__ float ws[4];
    if ((tid & 31) == 0) ws[tid >> 5] = s;
    __syncthreads();
    if (tid == 0) out[b] = ws[0] + ws[1] + ws[2] + ws[3] + fcb[0];
}

extern "C" void kernel_launch(void* const* d_in, const int* in_sizes, int n_in,
                              void* d_out, int out_size)
{
    const float* x     = (const float*)d_in[0];
    const float* W_ih0 = (const float*)d_in[1];
    const float* W_hh0 = (const float*)d_in[2];
    const float* b_ih0 = (const float*)d_in[3];
    const float* b_hh0 = (const float*)d_in[4];
    const float* W_ih1 = (const float*)d_in[5];
    const float* W_hh1 = (const float*)d_in[6];
    const float* b_ih1 = (const float*)d_in[7];
    const float* b_hh1 = (const float*)d_in[8];
    const float* fc_w  = (const float*)d_in[9];
    const float* fc_b  = (const float*)d_in[10];
    float* out = (float*)d_out;

    // dynamic SMEM sizes (bytes)
    const size_t sm0 = (size_t)(64 * (DD + HH + 4) + 8 * (DD + HH) + 512 + 128) * 4;  //  95,744
    const size_t sm1 = (size_t)(64 * (HH + HH + 4) + 8 * (HH + HH) + 512 + 128) * 4;  // 151,040

    cudaFuncSetAttribute(rnn_layer<DD>, cudaFuncAttributeMaxDynamicSharedMemorySize, (int)sm0);
    cudaFuncSetAttribute(rnn_layer<HH>, cudaFuncAttributeMaxDynamicSharedMemorySize, (int)sm1);

    // Layer 0: input = x [B][T][D]  -> SB = T*D, ST = D
    rnn_layer<DD><<<NCTAS, NTHREADS, sm0>>>(
        x, (long long)TT * DD, (long long)DD,
        W_ih0, W_hh0, b_ih0, b_hh0, /*in_sel=*/0, /*out_sel=*/0);

    // Layer 1: input = d_h1s [T][B][H] -> SB = H, ST = B*H
    rnn_layer<HH><<<NCTAS, NTHREADS, sm1>>>(
        nullptr, (long long)HH, (long long)BB * HH,
        W_ih1, W_hh1, b_ih1, b_hh1, /*in_sel=*/1, /*out_sel=*/1);

    fc_kernel<<<BB, 128>>>(fc_w, fc_b, out);
}

// round 2
// speedup vs baseline: 1.2339x; 1.2339x over previous
#include <cuda_runtime.h>
#include <cstdint>

#define BB 64
#define TT 1024
#define DD 64
#define HH 256
#define NGROUPS 8
#define NSLICES 16
#define BPG 8      // batches per group
#define UPS 16     // hidden units per slice
#define NCTAS (NGROUPS*NSLICES)
#define NTHREADS 256

// ---------------- device-global scratch (no runtime allocation allowed) ----------------
__device__ float    d_h1s[(size_t)TT * BB * HH];   // layer-0 hidden stream [T][B][H]
__device__ float    d_h2s[(size_t)TT * BB * HH];   // layer-1 hidden stream [T][B][H]
__device__ float    d_hbuf[2 * BB * HH];           // ping-pong h state
__device__ unsigned d_cnt[NGROUPS * 32];           // barrier arrive counters (128B apart)
__device__ unsigned d_gen[NGROUPS * 32];           // barrier generations

// Barrier across the 16 CTAs of one batch group. Generation-based, monotonic ->
// safe across graph replays and across the two layer launches.
__device__ __forceinline__ void group_barrier(int g) {
    __syncthreads();
    if (threadIdx.x == 0) {
        __threadfence();
        unsigned* cnt = &d_cnt[g * 32];
        unsigned* gen = &d_gen[g * 32];
        unsigned my = *(volatile unsigned*)gen;
        unsigned arrived = atomicAdd(cnt, 1u);
        if (arrived == NSLICES - 1) {
            atomicExch(cnt, 0u);
            __threadfence();
            atomicAdd(gen, 1u);
        } else {
            while (*(volatile unsigned*)gen == my) __nanosleep(32);
        }
        __threadfence();
    }
    __syncthreads();
}

__device__ __forceinline__ float sigf(float x) { return 1.f / (1.f + expf(-x)); }

// One LSTM layer, persistent. gates = [x_t | h_{t-1}] @ [W_ih | W_hh]^T + (b_ih + b_hh).
// Grid: 128 CTAs = 8 batch groups x 16 hidden slices. CTA owns 64 gate rows
// (4 gates x 16 units) for 8 batch elements.
// Thread tile: 1 gate row x (KTOT/4 k-range) x 8 batches (accumulators in regs).
template <int KIN>
__global__ void __launch_bounds__(NTHREADS, 1) rnn_layer(
    const float* __restrict__ xin, long long SBv, long long STv,
    const float* __restrict__ Wih, const float* __restrict__ Whh,
    const float* __restrict__ bih, const float* __restrict__ bhh,
    int in_sel, int out_sel)
{
    constexpr int KTOT = KIN + HH;
    constexpr int SP   = KTOT + 4;        // padded row stride; (SP/4) odd -> conflict-free LDS.128
    constexpr int KQ   = KTOT / 4;        // per-thread k span (4-way k split)
    constexpr int PSTR = 64 * 9;          // partial-sum kq stride (row pad 9)

    extern __shared__ float sm[];
    float* sW = sm;                        // [64][SP]
    float* sV = sW + 64 * SP;              // [8][KTOT]   staged [x_t | h_prev]
    float* sP = sV + 8 * KTOT;             // [4][64*9]   k-quarter partial sums
    float* sG = sP + 4 * PSTR;             // [64][8]     gate pre-activations
    float* sC = sG + 512;                  // [16][8]     cell state
    float* sB = sC + 128;                  // [64]        combined bias

    const float* in = in_sel ? d_h1s : xin;
    float*       hs = out_sel ? d_h2s : d_h1s;

    const int cta   = blockIdx.x;
    const int grp   = cta >> 4;            // batch group 0..7
    const int sl    = cta & 15;            // hidden slice 0..15
    const int bbase = grp * BPG;
    const int ubase = sl * UPS;
    const int tid   = threadIdx.x;

    // ---- one-time: load combined weight slice [64 rows][KIN | H] into SMEM ----
    for (int idx = tid; idx < 64 * KTOT; idx += NTHREADS) {
        int r = idx / KTOT, k = idx - r * KTOT;
        int R = ((r >> 4) << 8) + ubase + (r & 15);   // global gate row
        float v = (k < KIN) ? Wih[(long long)R * KIN + k]
                            : Whh[(long long)R * HH + (k - KIN)];
        sW[r * SP + k] = v;
    }
    if (tid < 64) {
        int R = ((tid >> 4) << 8) + ubase + (tid & 15);
        sB[tid] = bih[R] + bhh[R];
    }

    // ---- init c = 0 and zero own slice of hbuf[0] ----
    if (tid < 128) {
        int u = tid & 15, b = tid >> 4;
        sC[u * 8 + b] = 0.f;
        d_hbuf[(bbase + b) * HH + ubase + u] = 0.f;
    }
    __threadfence();
    group_barrier(grp);    // all slices of this group zeroed; sW/sB also visible

    const int rr = tid & 63;               // local gate row
    const int kq = tid >> 6;               // k quarter 0..3 (uniform within a warp)

    for (int t = 0; t < TT; ++t) {
        const int rb = t & 1;
        const float* hrd = d_hbuf + rb * (BB * HH);
        float*       hwr = d_hbuf + (rb ^ 1) * (BB * HH);

        // ---- stage input vector [x_t | h_prev] for 8 batches ----
        constexpr int K4 = KIN / 4;
        for (int idx = tid; idx < 8 * K4; idx += NTHREADS) {
            int b = idx / K4, k4 = idx - b * K4;
            reinterpret_cast<float4*>(sV + b * KTOT)[k4] =
                reinterpret_cast<const float4*>(
                    in + (long long)(bbase + b) * SBv + (long long)t * STv)[k4];
        }
        for (int idx = tid; idx < 8 * (HH / 4); idx += NTHREADS) {
            int b = idx >> 6, k4 = idx & 63;
            reinterpret_cast<float4*>(sV + b * KTOT + KIN)[k4] =
                reinterpret_cast<const float4*>(hrd + (bbase + b) * HH)[k4];
        }
        __syncthreads();

        // ---- dot products: thread = 1 gate row x 8 batches over its k quarter ----
        {
            const float* wrow = sW + rr * SP + kq * KQ;
            const float* vb   = sV + kq * KQ;
            float a0 = 0.f, a1 = 0.f, a2 = 0.f, a3 = 0.f;
            float a4 = 0.f, a5 = 0.f, a6 = 0.f, a7 = 0.f;
#pragma unroll 4
            for (int k = 0; k < KQ; k += 4) {
                float4 w  = *reinterpret_cast<const float4*>(wrow + k);
                float4 p0 = *reinterpret_cast<const float4*>(vb + 0 * KTOT + k);
                float4 p1 = *reinterpret_cast<const float4*>(vb + 1 * KTOT + k);
                float4 p2 = *reinterpret_cast<const float4*>(vb + 2 * KTOT + k);
                float4 p3 = *reinterpret_cast<const float4*>(vb + 3 * KTOT + k);
                float4 p4 = *reinterpret_cast<const float4*>(vb + 4 * KTOT + k);
                float4 p5 = *reinterpret_cast<const float4*>(vb + 5 * KTOT + k);
                float4 p6 = *reinterpret_cast<const float4*>(vb + 6 * KTOT + k);
                float4 p7 = *reinterpret_cast<const float4*>(vb + 7 * KTOT + k);
                a0 += w.x * p0.x; a0 += w.y * p0.y; a0 += w.z * p0.z; a0 += w.w * p0.w;
                a1 += w.x * p1.x; a1 += w.y * p1.y; a1 += w.z * p1.z; a1 += w.w * p1.w;
                a2 += w.x * p2.x; a2 += w.y * p2.y; a2 += w.z * p2.z; a2 += w.w * p2.w;
                a3 += w.x * p3.x; a3 += w.y * p3.y; a3 += w.z * p3.z; a3 += w.w * p3.w;
                a4 += w.x * p4.x; a4 += w.y * p4.y; a4 += w.z * p4.z; a4 += w.w * p4.w;
                a5 += w.x * p5.x; a5 += w.y * p5.y; a5 += w.z * p5.z; a5 += w.w * p5.w;
                a6 += w.x * p6.x; a6 += w.y * p6.y; a6 += w.z * p6.z; a6 += w.w * p6.w;
                a7 += w.x * p7.x; a7 += w.y * p7.y; a7 += w.z * p7.z; a7 += w.w * p7.w;
            }
            float* pp = sP + kq * PSTR + rr * 9;
            pp[0] = a0; pp[1] = a1; pp[2] = a2; pp[3] = a3;
            pp[4] = a4; pp[5] = a5; pp[6] = a6; pp[7] = a7;
        }
        __syncthreads();

        // ---- reduce 4 k-quarters -> gate pre-activations ----
        for (int o = tid; o < 512; o += NTHREADS) {
            int r = o >> 3, b = o & 7;
            int pi = r * 9 + b;
            sG[o] = sB[r] + sP[pi] + sP[PSTR + pi] + sP[2 * PSTR + pi] + sP[3 * PSTR + pi];
        }
        __syncthreads();

        // ---- elementwise update: thread = (unit, batch) ----
        if (tid < 128) {
            int u = tid & 15, b = tid >> 4;
            float gi = sG[(u)      * 8 + b];
            float gf = sG[(16 + u) * 8 + b];
            float gg = sG[(32 + u) * 8 + b];
            float go = sG[(48 + u) * 8 + b];
            float i = sigf(gi);
            float f = sigf(gf);
            float g = tanhf(gg);
            float o = sigf(go);
            float c = f * sC[u * 8 + b] + i * g;
            sC[u * 8 + b] = c;
            float hv = o * tanhf(c);
            hwr[(bbase + b) * HH + ubase + u] = hv;
            hs[((long long)t * BB + (bbase + b)) * HH + ubase + u] = hv;
        }
        __threadfence();
        group_barrier(grp);
    }
}

// out[b] = dot(h2[T-1][b][:], fc_w) + fc_b
__global__ void fc_kernel(const float* __restrict__ fcw,
                          const float* __restrict__ fcb,
                          float* __restrict__ out)
{
    int b = blockIdx.x, tid = threadIdx.x;
    const float* h = d_h2s + ((long long)(TT - 1) * BB + b) * HH;
    float s = 0.f;
    for (int k = tid; k < HH; k += 128) s += h[k] * fcw[k];
    for (int o = 16; o > 0; o >>= 1) s += __shfl_xor_sync(0xFFFFFFFFu, s, o);
    __shared__ float ws[4];
    if ((tid & 31) == 0) ws[tid >> 5] = s;
    __syncthreads();
    if (tid == 0) out[b] = ws[0] + ws[1] + ws[2] + ws[3] + fcb[0];
}

extern "C" void kernel_launch(void* const* d_in, const int* in_sizes, int n_in,
                              void* d_out, int out_size)
{
    const float* x     = (const float*)d_in[0];
    const float* W_ih0 = (const float*)d_in[1];
    const float* W_hh0 = (const float*)d_in[2];
    const float* b_ih0 = (const float*)d_in[3];
    const float* b_hh0 = (const float*)d_in[4];
    const float* W_ih1 = (const float*)d_in[5];
    const float* W_hh1 = (const float*)d_in[6];
    const float* b_ih1 = (const float*)d_in[7];
    const float* b_hh1 = (const float*)d_in[8];
    const float* fc_w  = (const float*)d_in[9];
    const float* fc_b  = (const float*)d_in[10];
    float* out = (float*)d_out;

    // dynamic SMEM sizes (bytes)
    const size_t sm0 = (size_t)(64 * (DD + HH + 4) + 8 * (DD + HH) + 4 * 64 * 9 + 512 + 128 + 64) * 4;
    const size_t sm1 = (size_t)(64 * (HH + HH + 4) + 8 * (HH + HH) + 4 * 64 * 9 + 512 + 128 + 64) * 4;

    cudaFuncSetAttribute(rnn_layer<DD>, cudaFuncAttributeMaxDynamicSharedMemorySize, (int)sm0);
    cudaFuncSetAttribute(rnn_layer<HH>, cudaFuncAttributeMaxDynamicSharedMemorySize, (int)sm1);

    // Layer 0: input = x [B][T][D]  -> SB = T*D, ST = D
    rnn_layer<DD><<<NCTAS, NTHREADS, sm0>>>(
        x, (long long)TT * DD, (long long)DD,
        W_ih0, W_hh0, b_ih0, b_hh0, /*in_sel=*/0, /*out_sel=*/0);

    // Layer 1: input = d_h1s [T][B][H] -> SB = H, ST = B*H
    rnn_layer<HH><<<NCTAS, NTHREADS, sm1>>>(
        nullptr, (long long)HH, (long long)BB * HH,
        W_ih1, W_hh1, b_ih1, b_hh1, /*in_sel=*/1, /*out_sel=*/1);

    fc_kernel<<<BB, 128>>>(fc_w, fc_b, out);
}